// round 5
// baseline (speedup 1.0000x reference)
#include <cuda_runtime.h>
#include <cuda_bf16.h>

#define NB 16
#define NA 49104
#define PRE_CAP 12288
#define PRE_BITS 0x3F400000u   // 0.75f ; bin boundary at (bits>>20)==0x3F4

// ---------------- scratch (device globals) ----------------
__device__ float g_score[NB * NA];
__device__ int   g_h1[NB * 4096];
__device__ int   g_cnt[NB];
__device__ int   g_pcnt[NB];
__device__ int   g_pover[NB];
__device__ unsigned long long g_pre[NB * PRE_CAP];
__device__ unsigned long long g_cand[NB * 1024];

__device__ float g_topScore[NB * 1024];
__device__ float g_topCls[NB * 1024];
__device__ float g_topTheta[NB * 1024];
__device__ float g_topBox[NB * 1024 * 4];

__device__ unsigned g_W[NB * 32 * 1024];  // [b][g][j] : bit i = iou(i=g*32+i, j)>thr && i<j
__device__ unsigned g_U[NB * 1024];       // [b][g*32+i] : intra-group row (suppressor i)

struct Ptrs { const float* p[20]; };

__device__ __forceinline__ void level_of(int a, int& l, int& p, int& h, int& s) {
    if (a < 36864)      { l = 0; p = a;         h = 192; s = 8;   }
    else if (a < 46080) { l = 1; p = a - 36864; h = 96;  s = 16;  }
    else if (a < 48384) { l = 2; p = a - 46080; h = 48;  s = 32;  }
    else if (a < 48960) { l = 3; p = a - 48384; h = 24;  s = 64;  }
    else                { l = 4; p = a - 48960; h = 12;  s = 128; }
}

// ---------------- kernel 0: zero state ----------------
__global__ void zero_kernel() {
    int t = blockIdx.x * blockDim.x + threadIdx.x;
    int n = blockDim.x * gridDim.x;
    for (int i = t; i < NB * 4096; i += n) g_h1[i] = 0;
    if (t < NB) { g_cnt[t] = 0; g_pcnt[t] = 0; g_pover[t] = 0; }
}

// ---------------- kernel 1: scores + L1 hist + prelist (block-aggregated) ----------------
__global__ void __launch_bounds__(256) score_hist_kernel(Ptrs in) {
    __shared__ int hist[4096];
    __shared__ int wtot[8];
    __shared__ int sBase;
    int b = blockIdx.y, bx = blockIdx.x, tid = threadIdx.x;
    int lane = tid & 31, wd = tid >> 5;
    for (int i = tid; i < 4096; i += 256) hist[i] = 0;
    __syncthreads();

    int base = bx * 1024 + tid * 4;   // 4 anchors per thread, never crosses level bound
    unsigned kb[4];
    int cntP = 0;
    bool act = base < NA;
    if (act) {
        int l, p, h, s; level_of(base, l, p, h, s);
        int hh = h * h;
        const float4* cls = (const float4*)(in.p[l] + b * 15 * hh + p);
        int st = hh >> 2;
        float4 m4 = cls[0];
#pragma unroll
        for (int c = 1; c < 15; c++) {
            float4 v = cls[c * st];
            m4.x = fmaxf(m4.x, v.x); m4.y = fmaxf(m4.y, v.y);
            m4.z = fmaxf(m4.z, v.z); m4.w = fmaxf(m4.w, v.w);
        }
        float4 sc;
        sc.x = 1.0f / (1.0f + expf(-m4.x));
        sc.y = 1.0f / (1.0f + expf(-m4.y));
        sc.z = 1.0f / (1.0f + expf(-m4.z));
        sc.w = 1.0f / (1.0f + expf(-m4.w));
        *(float4*)&g_score[b * NA + base] = sc;
        kb[0] = __float_as_uint(sc.x); kb[1] = __float_as_uint(sc.y);
        kb[2] = __float_as_uint(sc.z); kb[3] = __float_as_uint(sc.w);
#pragma unroll
        for (int q = 0; q < 4; q++) {
            atomicAdd(&hist[kb[q] >> 20], 1);
            cntP += (kb[q] >= PRE_BITS);
        }
    }
    // block-aggregated prelist append: warp shuffle scan + one global atomic per block
    int inc = cntP;
#pragma unroll
    for (int d = 1; d < 32; d <<= 1) {
        int t = __shfl_up_sync(0xffffffffu, inc, d);
        if (lane >= d) inc += t;
    }
    if (lane == 31) wtot[wd] = inc;
    __syncthreads();
    if (tid == 0) {
        int tot = 0;
#pragma unroll
        for (int w = 0; w < 8; w++) { int t = wtot[w]; wtot[w] = tot; tot += t; }
        sBase = tot ? atomicAdd(&g_pcnt[b], tot) : 0;
    }
    __syncthreads();
    if (act && cntP) {
        int off = sBase + wtot[wd] + (inc - cntP);
#pragma unroll
        for (int q = 0; q < 4; q++) {
            if (kb[q] >= PRE_BITS) {
                if (off < PRE_CAP)
                    g_pre[b * PRE_CAP + off] = ((unsigned long long)kb[q] << 32) | (unsigned)(base + q);
                else
                    g_pover[b] = 1;
                off++;
            }
        }
    }
    __syncthreads();
    for (int i = tid; i < 4096; i += 256) {
        int v = hist[i];
        if (v) atomicAdd(&g_h1[b * 4096 + i], v);
    }
}

// ---------------- threshold finder over a shared histogram ----------------
__device__ __forceinline__ void find_thresh(const int* h, int nbins, int target,
                                            int* partial, int* res, int tid,
                                            int& T, int& acc) {
    int spb = nbins >> 8;
    if (tid < 256) { int s = 0; for (int i = 0; i < spb; i++) s += h[tid * spb + i]; partial[tid] = s; }
    __syncthreads();
    if (tid == 0) {
        int a = 0, TT = 0;
        for (int seg = 255; seg >= 0; seg--) {
            int ps = partial[seg];
            if (a + ps >= target) {
                for (int bin = seg * spb + spb - 1;; bin--) {
                    int hc = h[bin];
                    if (a + hc >= target) { TT = bin; break; }
                    a += hc;
                }
                break;
            }
            a += ps;
        }
        res[0] = TT; res[1] = a;
    }
    __syncthreads();
    T = res[0]; acc = res[1];
}

// ---------------- ballot-aggregated emit of one item ----------------
__device__ __forceinline__ void emit_item(bool em, unsigned k, unsigned a, int b,
                                          int* sCnt, int lane) {
    unsigned mv = __ballot_sync(0xffffffffu, em);
    if (mv) {
        int ldr = __ffs(mv) - 1;
        int pos = 0;
        if (lane == ldr) pos = atomicAdd(sCnt, __popc(mv));
        pos = __shfl_sync(0xffffffffu, pos, ldr);
        if (em) {
            int o = pos + __popc(mv & ((1u << lane) - 1));
            if (o < 1024)
                g_cand[b * 1024 + o] = ((unsigned long long)(~k) << 32) | a;
        }
    }
}

// ---------------- kernel 2: per-batch T1/T2/T3 selection + emission ----------------
__global__ void __launch_bounds__(1024) select_emit_kernel() {
    __shared__ int h[4096];
    __shared__ int partial[256];
    __shared__ int res[2];
    __shared__ int h3[256];
    __shared__ int sCnt;
    int b = blockIdx.x, tid = threadIdx.x, lane = tid & 31;

    // ---- T1 from global 12-bit hist ----
    for (int i = tid; i < 4096; i += 1024) h[i] = g_h1[b * 4096 + i];
    __syncthreads();
    int T1, acc1;
    find_thresh(h, 4096, 1000, partial, res, tid, T1, acc1);
    __syncthreads();

    int pcnt = min(g_pcnt[b], PRE_CAP);
    bool usable = (T1 >= (int)(PRE_BITS >> 20)) && (g_pover[b] == 0);

    for (int i = tid; i < 4096; i += 1024) h[i] = 0;
    if (tid < 256) h3[tid] = 0;
    if (tid == 0) sCnt = 0;
    __syncthreads();

    const unsigned long long* pre = g_pre + b * PRE_CAP;
    const float* sc = g_score + b * NA;
    int nIt = usable ? ((pcnt + 1023) >> 10) : 48;

    // ---- pass 1: emit bin>T1 ; hist mid-12-bits for bin==T1 ----
    for (int it = 0; it < nIt; it++) {
        int i = it * 1024 + tid;
        unsigned k = 0, a = 0; bool em = false;
        if (usable) {
            if (i < pcnt) {
                unsigned long long v = pre[i];
                k = (unsigned)(v >> 32); a = (unsigned)v;
                int bin = (int)(k >> 20);
                if (bin > T1) em = true;
                else if (bin == T1) atomicAdd(&h[(k >> 8) & 0xFFF], 1);
            }
        } else {
            if (i < NA) {
                k = __float_as_uint(sc[i]); a = (unsigned)i;
                int bin = (int)(k >> 20);
                if (bin > T1) em = true;
                else if (bin == T1) atomicAdd(&h[(k >> 8) & 0xFFF], 1);
            }
        }
        emit_item(em, k, a, b, &sCnt, lane);
    }
    __syncthreads();

    // ---- T2 ----
    int T2, acc2;
    find_thresh(h, 4096, 1000 - acc1, partial, res, tid, T2, acc2);
    __syncthreads();

    // ---- pass 2: h3 over low byte of bin==T1 && mid==T2 ----
    for (int it = 0; it < nIt; it++) {
        int i = it * 1024 + tid;
        if (usable) {
            if (i < pcnt) {
                unsigned k = (unsigned)(pre[i] >> 32);
                if ((int)(k >> 20) == T1 && (int)((k >> 8) & 0xFFF) == T2)
                    atomicAdd(&h3[k & 0xFF], 1);
            }
        } else {
            if (i < NA) {
                unsigned k = __float_as_uint(sc[i]);
                if ((int)(k >> 20) == T1 && (int)((k >> 8) & 0xFFF) == T2)
                    atomicAdd(&h3[k & 0xFF], 1);
            }
        }
    }
    __syncthreads();
    if (tid == 0) {
        int tg = 1000 - acc1 - acc2, a = 0, T = 0;
        for (int bin = 255;; bin--) {
            int hc = h3[bin];
            if (a + hc >= tg) { T = bin; break; }
            a += hc;
        }
        res[0] = T;
    }
    __syncthreads();
    int T3 = res[0];

    // ---- pass 3: emit bin==T1 && (mid>T2 || (mid==T2 && low>=T3)) ----
    for (int it = 0; it < nIt; it++) {
        int i = it * 1024 + tid;
        unsigned k = 0, a = 0; bool em = false;
        if (usable) {
            if (i < pcnt) {
                unsigned long long v = pre[i];
                k = (unsigned)(v >> 32); a = (unsigned)v;
            } else k = 0;
        } else {
            if (i < NA) { k = __float_as_uint(sc[i]); a = (unsigned)i; }
        }
        if (k && (int)(k >> 20) == T1) {
            int mid = (int)((k >> 8) & 0xFFF);
            em = (mid > T2) || (mid == T2 && (int)(k & 0xFF) >= T3);
        }
        emit_item(em, k, a, b, &sCnt, lane);
    }
    __syncthreads();
    if (tid == 0) g_cnt[b] = sCnt;
}

// ---------------- kernel 3: per-batch sort 1024 + winner decode ----------------
__global__ void __launch_bounds__(1024) sort_decode_kernel(Ptrs in) {
    __shared__ unsigned long long cand[1024];
    int b = blockIdx.x, tid = threadIdx.x;
    int c = min(g_cnt[b], 1024);
    cand[tid] = (tid < c) ? g_cand[b * 1024 + tid] : 0xFFFFFFFFFFFFFFFFULL;
    __syncthreads();

    for (int k2 = 2; k2 <= 32; k2 <<= 1) {
        for (int s2 = k2 >> 1; s2 > 0; s2 >>= 1) {
            __syncwarp();
            int q = tid ^ s2;
            if (q > tid) {
                bool asc = ((tid & k2) == 0);
                unsigned long long A = cand[tid], Bv = cand[q];
                if ((A > Bv) == asc) { cand[tid] = Bv; cand[q] = A; }
            }
        }
    }
    for (int k2 = 64; k2 <= 1024; k2 <<= 1) {
        for (int s2 = k2 >> 1; s2 > 0; s2 >>= 1) {
            if (s2 >= 16) __syncthreads(); else __syncwarp();
            int q = tid ^ s2;
            if (q > tid) {
                bool asc = ((tid & k2) == 0);
                unsigned long long A = cand[tid], Bv = cand[q];
                if ((A > Bv) == asc) { cand[tid] = Bv; cand[q] = A; }
            }
        }
    }
    __syncthreads();

    int o = b * 1024 + tid;
    if (tid < 1000) {
        unsigned long long v = cand[tid];
        int a = (int)(unsigned)(v & 0xFFFFFFFFu);
        float score = __uint_as_float(~(unsigned)(v >> 32));

        int l, p, h, s; level_of(a, l, p, h, s);
        int hh = h * h;
        const float* cls = in.p[l]      + b * 15 * hh + p;
        const float* reg = in.p[5 + l]  + b * 5  * hh + p;
        const float* tcp = in.p[10 + l] + b * 18 * hh + p;
        const float* trp = in.p[15 + l] + b * hh + p;

        float best = cls[0]; int bc = 0;
#pragma unroll
        for (int cc = 1; cc < 15; cc++) { float vv = cls[cc * hh]; if (vv > best) { best = vv; bc = cc; } }
        float tb = tcp[0]; int ta = 0;
#pragma unroll
        for (int cc = 1; cc < 18; cc++) { float vv = tcp[cc * hh]; if (vv > tb) { tb = vv; ta = cc; } }
        float theta = (float)(ta + 1) * 10.0f + trp[0];

        float fs = (float)s;
        int col = p % h, row = p / h;
        float x = (float)col * fs + (float)(s / 2);
        float y = (float)row * fs + (float)(s / 2);

        g_topScore[o] = score;
        g_topCls[o]   = (float)(bc + 1);
        g_topTheta[o] = theta;
        g_topBox[o * 4 + 0] = x - reg[0] * fs;
        g_topBox[o * 4 + 1] = y - reg[hh] * fs;
        g_topBox[o * 4 + 2] = x + reg[2 * hh] * fs;
        g_topBox[o * 4 + 3] = y + reg[3 * hh] * fs;
    } else {
        g_topScore[o] = -1e30f;
        g_topCls[o] = 0.f; g_topTheta[o] = 0.f;
        g_topBox[o * 4 + 0] = 0.f; g_topBox[o * 4 + 1] = 0.f;
        g_topBox[o * 4 + 2] = 0.f; g_topBox[o * 4 + 3] = 0.f;
    }
}

// ---------------- kernel 4: IoU bit-masks (fully parallel) ----------------
__global__ void __launch_bounds__(1024) mask_kernel() {
    int b = blockIdx.y, g = blockIdx.x, j = threadIdx.x;
    __shared__ float ib[32][4];
    if (j < 32) {
#pragma unroll
        for (int k = 0; k < 4; k++) ib[j][k] = g_topBox[(b * 1024 + g * 32 + j) * 4 + k];
    }
    __syncthreads();

    float x1 = g_topBox[(b * 1024 + j) * 4 + 0];
    float y1 = g_topBox[(b * 1024 + j) * 4 + 1];
    float x2 = g_topBox[(b * 1024 + j) * 4 + 2];
    float y2 = g_topBox[(b * 1024 + j) * 4 + 3];
    float area = fmaxf(x2 - x1, 0.f) * fmaxf(y2 - y1, 0.f);

    unsigned w = 0;
#pragma unroll
    for (int bb = 0; bb < 32; bb++) {
        int i = g * 32 + bb;
        float ix1 = ib[bb][0], iy1 = ib[bb][1], ix2 = ib[bb][2], iy2 = ib[bb][3];
        float iarea = fmaxf(ix2 - ix1, 0.f) * fmaxf(iy2 - iy1, 0.f);
        float iw = fmaxf(fminf(x2, ix2) - fmaxf(x1, ix1), 0.f);
        float ih = fmaxf(fminf(y2, iy2) - fmaxf(y1, iy1), 0.f);
        float inter = iw * ih;
        float uni = fmaxf(area + iarea - inter, 1e-8f);
        bool pred = (inter > 0.3f * uni) && (i < j);
        w |= ((unsigned)pred) << bb;
    }
    g_W[(b * 32 + g) * 1024 + j] = w;

    if ((j >> 5) == g) {
        int lane = j & 31;
        unsigned u = 0;
#pragma unroll
        for (int i = 0; i < 32; i++) {
            unsigned t = __ballot_sync(0xffffffffu, (w >> i) & 1u);
            if (lane == i) u = t;
        }
        g_U[b * 1024 + g * 32 + lane] = u;
    }
}

// ---------------- kernel 5: barrier-free pipelined greedy scan + output ----------------
__global__ void __launch_bounds__(1024) scan_kernel(float* __restrict__ out) {
    int b = blockIdx.x, j = threadIdx.x;
    int lane = j & 31, wid = j >> 5;
    __shared__ unsigned su[1024];
    __shared__ unsigned long long sm64[32];

    float score = g_topScore[b * 1024 + j];
    bool alive = (j < 1000) && (score >= 0.05f);

    unsigned su_own = g_U[b * 1024 + j];
    su[j] = su_own;
    if (j < 32) sm64[j] = 0ULL;
    unsigned nzm = __ballot_sync(0xffffffffu, su_own != 0u);
    __syncthreads();

    const unsigned* Wb = g_W + b * 32 * 1024;
    for (int g = 0; g < wid; g++) {
        unsigned wv = Wb[g * 1024 + j];
        unsigned long long v;
        do { v = *(volatile const unsigned long long*)&sm64[g]; } while (!(v >> 32));
        unsigned mg = (unsigned)v;
        alive = alive && ((wv & mg) == 0u);
    }
    unsigned m = __ballot_sync(0xffffffffu, alive);
    if (lane == 0) {
        unsigned todo = nzm & m;
        while (todo) {
            int bb = __ffs(todo) - 1;
            m &= ~su[wid * 32 + bb];
            todo &= todo - 1;
            todo &= m;
        }
        *(volatile unsigned long long*)&sm64[wid] = (1ULL << 32) | (unsigned long long)m;
    }
    m = __shfl_sync(0xffffffffu, m, 0);
    alive = (m >> lane) & 1u;

    if (j < 1000) {
        float k = alive ? 1.0f : 0.0f;
        int o = b * 1024 + j;
        out[b * 1000 + j] = score * k;
        out[16000 + b * 1000 + j] = k * g_topCls[o];
        int base = 32000 + (b * 1000 + j) * 5;
        out[base + 0] = k * g_topBox[o * 4 + 0];
        out[base + 1] = k * g_topBox[o * 4 + 1];
        out[base + 2] = k * g_topBox[o * 4 + 2];
        out[base + 3] = k * g_topBox[o * 4 + 3];
        out[base + 4] = k * g_topTheta[o];
    }
}

// ---------------- launch ----------------
extern "C" void kernel_launch(void* const* d_in, const int* in_sizes, int n_in,
                              void* d_out, int out_size) {
    Ptrs P;
    for (int i = 0; i < 20; i++) P.p[i] = (const float*)d_in[i];

    zero_kernel<<<32, 1024>>>();
    score_hist_kernel<<<dim3(48, NB), 256>>>(P);
    select_emit_kernel<<<NB, 1024>>>();
    sort_decode_kernel<<<NB, 1024>>>(P);
    mask_kernel<<<dim3(32, NB), 1024>>>();
    scan_kernel<<<NB, 1024>>>((float*)d_out);
}

// round 7
// speedup vs baseline: 1.0398x; 1.0398x over previous
#include <cuda_runtime.h>
#include <cuda_bf16.h>

#define NB 16
#define NA 49104
#define PRE_CAP 12288
#define PRE_BITS 0x3F400000u   // 0.75f ; bin boundary at (bits>>20)==0x3F4

// ---------------- scratch (device globals) ----------------
__device__ float g_score[NB * NA];
__device__ int   g_cnt[NB];
__device__ int   g_pcnt[NB];
__device__ int   g_pover[NB];
__device__ unsigned long long g_pre[NB * PRE_CAP];
__device__ unsigned long long g_cand[NB * 1024];

__device__ float g_topScore[NB * 1024];
__device__ float g_topCls[NB * 1024];
__device__ float g_topTheta[NB * 1024];
__device__ float g_topBox[NB * 1024 * 4];

__device__ unsigned g_W[NB * 32 * 1024];  // [b][g][j] : bit i = iou(i=g*32+i, j)>thr && i<j
__device__ unsigned g_U[NB * 1024];       // [b][g*32+i] : intra-group row (suppressor i)

struct Ptrs { const float* p[20]; };

__device__ __forceinline__ void level_of(int a, int& l, int& p, int& h, int& s) {
    if (a < 36864)      { l = 0; p = a;         h = 192; s = 8;   }
    else if (a < 46080) { l = 1; p = a - 36864; h = 96;  s = 16;  }
    else if (a < 48384) { l = 2; p = a - 46080; h = 48;  s = 32;  }
    else if (a < 48960) { l = 3; p = a - 48384; h = 24;  s = 64;  }
    else                { l = 4; p = a - 48960; h = 12;  s = 128; }
}

// ---------------- kernel 0: zero counters ----------------
__global__ void zero_kernel() {
    int t = threadIdx.x;
    if (t < NB) { g_pcnt[t] = 0; g_pover[t] = 0; }
}

// ---------------- kernel 1: scores + prelist (block-aggregated append) ----------------
__global__ void __launch_bounds__(256) score_pre_kernel(Ptrs in) {
    __shared__ int wtot[8];
    __shared__ int sBase;
    int b = blockIdx.y, bx = blockIdx.x, tid = threadIdx.x;
    int lane = tid & 31, wd = tid >> 5;

    int base = bx * 2048 + tid * 8;   // 8 anchors / thread; 4-groups never cross level bound
    unsigned kb[8];
    int cntP = 0;
    bool act = base < NA;
    if (act) {
#pragma unroll
        for (int q = 0; q < 2; q++) {
            int a0 = base + q * 4;
            int l, p, h, s; level_of(a0, l, p, h, s);
            int hh = h * h;
            const float4* cls = (const float4*)(in.p[l] + b * 15 * hh + p);
            int st = hh >> 2;
            float4 m4 = cls[0];
#pragma unroll
            for (int c = 1; c < 15; c++) {
                float4 v = cls[c * st];
                m4.x = fmaxf(m4.x, v.x); m4.y = fmaxf(m4.y, v.y);
                m4.z = fmaxf(m4.z, v.z); m4.w = fmaxf(m4.w, v.w);
            }
            float4 sc;
            sc.x = 1.0f / (1.0f + expf(-m4.x));
            sc.y = 1.0f / (1.0f + expf(-m4.y));
            sc.z = 1.0f / (1.0f + expf(-m4.z));
            sc.w = 1.0f / (1.0f + expf(-m4.w));
            *(float4*)&g_score[b * NA + a0] = sc;
            kb[q * 4 + 0] = __float_as_uint(sc.x);
            kb[q * 4 + 1] = __float_as_uint(sc.y);
            kb[q * 4 + 2] = __float_as_uint(sc.z);
            kb[q * 4 + 3] = __float_as_uint(sc.w);
        }
#pragma unroll
        for (int q = 0; q < 8; q++) cntP += (kb[q] >= PRE_BITS);
    }
    // block-aggregated prelist append: one global atomic per block
    int inc = cntP;
#pragma unroll
    for (int d = 1; d < 32; d <<= 1) {
        int t = __shfl_up_sync(0xffffffffu, inc, d);
        if (lane >= d) inc += t;
    }
    if (lane == 31) wtot[wd] = inc;
    __syncthreads();
    if (tid == 0) {
        int tot = 0;
#pragma unroll
        for (int w = 0; w < 8; w++) { int t = wtot[w]; wtot[w] = tot; tot += t; }
        sBase = tot ? atomicAdd(&g_pcnt[b], tot) : 0;
    }
    __syncthreads();
    if (act && cntP) {
        int off = sBase + wtot[wd] + (inc - cntP);
#pragma unroll
        for (int q = 0; q < 8; q++) {
            if (kb[q] >= PRE_BITS) {
                if (off < PRE_CAP)
                    g_pre[b * PRE_CAP + off] = ((unsigned long long)kb[q] << 32) | (unsigned)(base + q);
                else
                    g_pover[b] = 1;
                off++;
            }
        }
    }
}

// ---------------- threshold finder over a shared histogram ----------------
__device__ __forceinline__ void find_thresh(const int* h, int nbins, int target,
                                            int* partial, int* res, int tid,
                                            int& T, int& acc) {
    int spb = nbins >> 8;
    if (tid < 256) { int s = 0; for (int i = 0; i < spb; i++) s += h[tid * spb + i]; partial[tid] = s; }
    __syncthreads();
    if (tid == 0) {
        int a = 0, TT = 0;
        for (int seg = 255; seg >= 0; seg--) {
            int ps = partial[seg];
            if (a + ps >= target) {
                for (int bin = seg * spb + spb - 1;; bin--) {
                    int hc = h[bin];
                    if (a + hc >= target) { TT = bin; break; }
                    a += hc;
                }
                break;
            }
            a += ps;
        }
        res[0] = TT; res[1] = a;
    }
    __syncthreads();
    T = res[0]; acc = res[1];
}

// ---------------- ballot-aggregated emit ----------------
__device__ __forceinline__ void emit_item(bool em, unsigned k, unsigned a, int b,
                                          int* sCnt, int lane) {
    unsigned mv = __ballot_sync(0xffffffffu, em);
    if (mv) {
        int ldr = __ffs(mv) - 1;
        int pos = 0;
        if (lane == ldr) pos = atomicAdd(sCnt, __popc(mv));
        pos = __shfl_sync(0xffffffffu, pos, ldr);
        if (em) {
            int o = pos + __popc(mv & ((1u << lane) - 1));
            if (o < 1024)
                g_cand[b * 1024 + o] = ((unsigned long long)(~k) << 32) | a;
        }
    }
}

// ---------------- kernel 2: per-batch exact top-1000 selection + emission ----------------
__global__ void __launch_bounds__(1024) select_emit_kernel() {
    __shared__ int h[4096];
    __shared__ int partial[256];
    __shared__ int res[2];
    __shared__ int h3[256];
    __shared__ int sCnt;
    int b = blockIdx.x, tid = threadIdx.x, lane = tid & 31;

    int pcnt = min(g_pcnt[b], PRE_CAP);
    bool usable = (pcnt >= 1000) && (g_pover[b] == 0);

    const unsigned long long* pre = g_pre + b * PRE_CAP;
    const float* sc = g_score + b * NA;
    int nIt = usable ? ((pcnt + 1023) >> 10) : 48;

    for (int i = tid; i < 4096; i += 1024) h[i] = 0;
    if (tid == 0) sCnt = 0;
    __syncthreads();

    // ---- pass 0: 12-bit histogram ----
    for (int it = 0; it < nIt; it++) {
        int i = it * 1024 + tid;
        if (usable) {
            if (i < pcnt) atomicAdd(&h[(unsigned)(pre[i] >> 52)], 1);
        } else {
            if (i < NA) atomicAdd(&h[__float_as_uint(sc[i]) >> 20], 1);
        }
    }
    __syncthreads();
    int T1, acc1;
    find_thresh(h, 4096, 1000, partial, res, tid, T1, acc1);
    __syncthreads();
    for (int i = tid; i < 4096; i += 1024) h[i] = 0;
    if (tid < 256) h3[tid] = 0;
    __syncthreads();

    // ---- pass 1: emit bin>T1 ; hist mid-12 for bin==T1 ----
    for (int it = 0; it < nIt; it++) {
        int i = it * 1024 + tid;
        unsigned k = 0, a = 0; bool em = false;
        if (usable) {
            if (i < pcnt) {
                unsigned long long v = pre[i];
                k = (unsigned)(v >> 32); a = (unsigned)v;
            }
        } else if (i < NA) { k = __float_as_uint(sc[i]); a = (unsigned)i; }
        if (k) {
            int bin = (int)(k >> 20);
            if (bin > T1) em = true;
            else if (bin == T1) atomicAdd(&h[(k >> 8) & 0xFFF], 1);
        }
        emit_item(em, k, a, b, &sCnt, lane);
    }
    __syncthreads();
    int T2, acc2;
    find_thresh(h, 4096, 1000 - acc1, partial, res, tid, T2, acc2);
    __syncthreads();

    // ---- pass 2: low-byte hist for bin==T1 && mid==T2 ----
    for (int it = 0; it < nIt; it++) {
        int i = it * 1024 + tid;
        unsigned k = 0;
        if (usable) { if (i < pcnt) k = (unsigned)(pre[i] >> 32); }
        else if (i < NA) k = __float_as_uint(sc[i]);
        if (k && (int)(k >> 20) == T1 && (int)((k >> 8) & 0xFFF) == T2)
            atomicAdd(&h3[k & 0xFF], 1);
    }
    __syncthreads();
    if (tid == 0) {
        int tg = 1000 - acc1 - acc2, a = 0, T = 0;
        for (int bin = 255;; bin--) {
            int hc = h3[bin];
            if (a + hc >= tg) { T = bin; break; }
            a += hc;
        }
        res[0] = T;
    }
    __syncthreads();
    int T3 = res[0];

    // ---- pass 3: emit remainder ----
    for (int it = 0; it < nIt; it++) {
        int i = it * 1024 + tid;
        unsigned k = 0, a = 0; bool em = false;
        if (usable) {
            if (i < pcnt) {
                unsigned long long v = pre[i];
                k = (unsigned)(v >> 32); a = (unsigned)v;
            }
        } else if (i < NA) { k = __float_as_uint(sc[i]); a = (unsigned)i; }
        if (k && (int)(k >> 20) == T1) {
            int mid = (int)((k >> 8) & 0xFFF);
            em = (mid > T2) || (mid == T2 && (int)(k & 0xFF) >= T3);
        }
        emit_item(em, k, a, b, &sCnt, lane);
    }
    __syncthreads();
    if (tid == 0) g_cnt[b] = sCnt;
}

// ---------------- kernel 3: per-batch key sort (bitonic 1024) ----------------
__global__ void __launch_bounds__(1024) sort_kernel() {
    __shared__ unsigned long long cand[1024];
    int b = blockIdx.x, tid = threadIdx.x;
    int c = min(g_cnt[b], 1024);
    cand[tid] = (tid < c) ? g_cand[b * 1024 + tid] : 0xFFFFFFFFFFFFFFFFULL;
    __syncthreads();

    for (int k2 = 2; k2 <= 32; k2 <<= 1) {
        for (int s2 = k2 >> 1; s2 > 0; s2 >>= 1) {
            __syncwarp();
            int q = tid ^ s2;
            if (q > tid) {
                bool asc = ((tid & k2) == 0);
                unsigned long long A = cand[tid], Bv = cand[q];
                if ((A > Bv) == asc) { cand[tid] = Bv; cand[q] = A; }
            }
        }
    }
    for (int k2 = 64; k2 <= 1024; k2 <<= 1) {
        for (int s2 = k2 >> 1; s2 > 0; s2 >>= 1) {
            if (s2 >= 16) __syncthreads(); else __syncwarp();
            int q = tid ^ s2;
            if (q > tid) {
                bool asc = ((tid & k2) == 0);
                unsigned long long A = cand[tid], Bv = cand[q];
                if ((A > Bv) == asc) { cand[tid] = Bv; cand[q] = A; }
            }
        }
    }
    __syncthreads();
    g_cand[b * 1024 + tid] = cand[tid];
}

// ---------------- kernel 4: parallel winner decode (1 thread / winner) ----------------
__global__ void __launch_bounds__(256) decode_kernel(Ptrs in) {
    __shared__ int sC;
    int b = blockIdx.y;
    if (threadIdx.x == 0) sC = g_cnt[b];
    __syncthreads();
    int w = blockIdx.x * 256 + threadIdx.x;   // 0..1023
    int o = b * 1024 + w;
    if (w < 1000 && w < sC) {
        unsigned long long v = g_cand[o];
        int a = (int)(unsigned)(v & 0xFFFFFFFFu);
        float score = __uint_as_float(~(unsigned)(v >> 32));

        int l, p, h, s; level_of(a, l, p, h, s);
        int hh = h * h;
        const float* cls = in.p[l]      + b * 15 * hh + p;
        const float* reg = in.p[5 + l]  + b * 5  * hh + p;
        const float* tcp = in.p[10 + l] + b * 18 * hh + p;
        const float* trp = in.p[15 + l] + b * hh + p;

        float best = cls[0]; int bc = 0;
#pragma unroll
        for (int cc = 1; cc < 15; cc++) { float vv = cls[cc * hh]; if (vv > best) { best = vv; bc = cc; } }
        float tb = tcp[0]; int ta = 0;
#pragma unroll
        for (int cc = 1; cc < 18; cc++) { float vv = tcp[cc * hh]; if (vv > tb) { tb = vv; ta = cc; } }
        float theta = (float)(ta + 1) * 10.0f + trp[0];

        float fs = (float)s;
        int col = p % h, row = p / h;
        float x = (float)col * fs + (float)(s / 2);
        float y = (float)row * fs + (float)(s / 2);

        g_topScore[o] = score;
        g_topCls[o]   = (float)(bc + 1);
        g_topTheta[o] = theta;
        g_topBox[o * 4 + 0] = x - reg[0] * fs;
        g_topBox[o * 4 + 1] = y - reg[hh] * fs;
        g_topBox[o * 4 + 2] = x + reg[2 * hh] * fs;
        g_topBox[o * 4 + 3] = y + reg[3 * hh] * fs;
    } else {
        g_topScore[o] = -1e30f;
        g_topCls[o] = 0.f; g_topTheta[o] = 0.f;
        g_topBox[o * 4 + 0] = 0.f; g_topBox[o * 4 + 1] = 0.f;
        g_topBox[o * 4 + 2] = 0.f; g_topBox[o * 4 + 3] = 0.f;
    }
}

// ---------------- kernel 5: IoU bit-masks (fully parallel) ----------------
__global__ void __launch_bounds__(1024) mask_kernel() {
    int b = blockIdx.y, g = blockIdx.x, j = threadIdx.x;
    __shared__ float ib[32][4];
    if (j < 32) {
#pragma unroll
        for (int k = 0; k < 4; k++) ib[j][k] = g_topBox[(b * 1024 + g * 32 + j) * 4 + k];
    }
    __syncthreads();

    float x1 = g_topBox[(b * 1024 + j) * 4 + 0];
    float y1 = g_topBox[(b * 1024 + j) * 4 + 1];
    float x2 = g_topBox[(b * 1024 + j) * 4 + 2];
    float y2 = g_topBox[(b * 1024 + j) * 4 + 3];
    float area = fmaxf(x2 - x1, 0.f) * fmaxf(y2 - y1, 0.f);

    unsigned w = 0;
#pragma unroll
    for (int bb = 0; bb < 32; bb++) {
        int i = g * 32 + bb;
        float ix1 = ib[bb][0], iy1 = ib[bb][1], ix2 = ib[bb][2], iy2 = ib[bb][3];
        float iarea = fmaxf(ix2 - ix1, 0.f) * fmaxf(iy2 - iy1, 0.f);
        float iw = fmaxf(fminf(x2, ix2) - fmaxf(x1, ix1), 0.f);
        float ih = fmaxf(fminf(y2, iy2) - fmaxf(y1, iy1), 0.f);
        float inter = iw * ih;
        float uni = fmaxf(area + iarea - inter, 1e-8f);
        bool pred = (inter > 0.3f * uni) && (i < j);
        w |= ((unsigned)pred) << bb;
    }
    g_W[(b * 32 + g) * 1024 + j] = w;

    if ((j >> 5) == g) {
        int lane = j & 31;
        unsigned u = 0;
#pragma unroll
        for (int i = 0; i < 32; i++) {
            unsigned t = __ballot_sync(0xffffffffu, (w >> i) & 1u);
            if (lane == i) u = t;
        }
        g_U[b * 1024 + g * 32 + lane] = u;
    }
}

// ---------------- kernel 6: barrier-free pipelined greedy scan + output ----------------
__global__ void __launch_bounds__(1024) scan_kernel(float* __restrict__ out) {
    int b = blockIdx.x, j = threadIdx.x;
    int lane = j & 31, wid = j >> 5;
    __shared__ unsigned su[1024];
    __shared__ unsigned long long sm64[32];

    float score = g_topScore[b * 1024 + j];
    bool alive = (j < 1000) && (score >= 0.05f);

    unsigned su_own = g_U[b * 1024 + j];
    su[j] = su_own;
    if (j < 32) sm64[j] = 0ULL;
    unsigned nzm = __ballot_sync(0xffffffffu, su_own != 0u);
    __syncthreads();

    const unsigned* Wb = g_W + b * 32 * 1024;
    for (int g = 0; g < wid; g++) {
        unsigned wv = Wb[g * 1024 + j];
        unsigned long long v;
        do { v = *(volatile const unsigned long long*)&sm64[g]; } while (!(v >> 32));
        unsigned mg = (unsigned)v;
        alive = alive && ((wv & mg) == 0u);
    }
    unsigned m = __ballot_sync(0xffffffffu, alive);
    if (lane == 0) {
        unsigned todo = nzm & m;
        while (todo) {
            int bb = __ffs(todo) - 1;
            m &= ~su[wid * 32 + bb];
            todo &= todo - 1;
            todo &= m;
        }
        *(volatile unsigned long long*)&sm64[wid] = (1ULL << 32) | (unsigned long long)m;
    }
    m = __shfl_sync(0xffffffffu, m, 0);
    alive = (m >> lane) & 1u;

    if (j < 1000) {
        float k = alive ? 1.0f : 0.0f;
        int o = b * 1024 + j;
        out[b * 1000 + j] = score * k;
        out[16000 + b * 1000 + j] = k * g_topCls[o];
        int base = 32000 + (b * 1000 + j) * 5;
        out[base + 0] = k * g_topBox[o * 4 + 0];
        out[base + 1] = k * g_topBox[o * 4 + 1];
        out[base + 2] = k * g_topBox[o * 4 + 2];
        out[base + 3] = k * g_topBox[o * 4 + 3];
        out[base + 4] = k * g_topTheta[o];
    }
}

// ---------------- launch ----------------
extern "C" void kernel_launch(void* const* d_in, const int* in_sizes, int n_in,
                              void* d_out, int out_size) {
    Ptrs P;
    for (int i = 0; i < 20; i++) P.p[i] = (const float*)d_in[i];

    zero_kernel<<<1, 32>>>();
    score_pre_kernel<<<dim3(24, NB), 256>>>(P);
    select_emit_kernel<<<NB, 1024>>>();
    sort_kernel<<<NB, 1024>>>();
    decode_kernel<<<dim3(4, NB), 256>>>(P);
    mask_kernel<<<dim3(32, NB), 1024>>>();
    scan_kernel<<<NB, 1024>>>((float*)d_out);
}

// round 8
// speedup vs baseline: 1.5335x; 1.4748x over previous
#include <cuda_runtime.h>
#include <cuda_bf16.h>

#define NB 16
#define NA 49104
#define PRE_CAP 6144
#define PRE_BITS 0x3F700000u   // 0.9375f ; all prelist items have (bits>>20) >= 0x3F7

// ---------------- scratch (device globals) ----------------
__device__ float g_score[NB * NA];
__device__ int   g_pcnt[NB];
__device__ int   g_pover[NB];
__device__ unsigned long long g_pre[NB * PRE_CAP];

__device__ float g_topScore[NB * 1024];
__device__ float g_topCls[NB * 1024];
__device__ float g_topTheta[NB * 1024];
__device__ float g_topBox[NB * 1024 * 4];

__device__ unsigned g_W[NB * 32 * 1024];  // [b][g][j] : bit i = iou(i=g*32+i, j)>thr && i<j
__device__ unsigned g_U[NB * 1024];       // [b][g*32+i] : intra-group row (suppressor i)

struct Ptrs { const float* p[20]; };

__device__ __forceinline__ void level_of(int a, int& l, int& p, int& h, int& s) {
    if (a < 36864)      { l = 0; p = a;         h = 192; s = 8;   }
    else if (a < 46080) { l = 1; p = a - 36864; h = 96;  s = 16;  }
    else if (a < 48384) { l = 2; p = a - 46080; h = 48;  s = 32;  }
    else if (a < 48960) { l = 3; p = a - 48384; h = 24;  s = 64;  }
    else                { l = 4; p = a - 48960; h = 12;  s = 128; }
}

// ---------------- kernel 0: zero counters ----------------
__global__ void zero_kernel() {
    int t = threadIdx.x;
    if (t < NB) { g_pcnt[t] = 0; g_pover[t] = 0; }
}

// ---------------- kernel 1: scores + prelist (block-aggregated append) ----------------
__global__ void __launch_bounds__(256) score_pre_kernel(Ptrs in) {
    __shared__ int wtot[8];
    __shared__ int sBase;
    int b = blockIdx.y, bx = blockIdx.x, tid = threadIdx.x;
    int lane = tid & 31, wd = tid >> 5;

    int base = bx * 2048 + tid * 8;   // 8 anchors / thread; 4-groups never cross level bound
    unsigned kb[8];
    int cntP = 0;
    bool act = base < NA;
    if (act) {
#pragma unroll
        for (int q = 0; q < 2; q++) {
            int a0 = base + q * 4;
            int l, p, h, s; level_of(a0, l, p, h, s);
            int hh = h * h;
            const float4* cls = (const float4*)(in.p[l] + b * 15 * hh + p);
            int st = hh >> 2;
            float4 m4 = cls[0];
#pragma unroll
            for (int c = 1; c < 15; c++) {
                float4 v = cls[c * st];
                m4.x = fmaxf(m4.x, v.x); m4.y = fmaxf(m4.y, v.y);
                m4.z = fmaxf(m4.z, v.z); m4.w = fmaxf(m4.w, v.w);
            }
            float4 sc;
            sc.x = 1.0f / (1.0f + expf(-m4.x));
            sc.y = 1.0f / (1.0f + expf(-m4.y));
            sc.z = 1.0f / (1.0f + expf(-m4.z));
            sc.w = 1.0f / (1.0f + expf(-m4.w));
            *(float4*)&g_score[b * NA + a0] = sc;
            kb[q * 4 + 0] = __float_as_uint(sc.x);
            kb[q * 4 + 1] = __float_as_uint(sc.y);
            kb[q * 4 + 2] = __float_as_uint(sc.z);
            kb[q * 4 + 3] = __float_as_uint(sc.w);
        }
#pragma unroll
        for (int q = 0; q < 8; q++) cntP += (kb[q] >= PRE_BITS);
    }
    // block-aggregated prelist append: one global atomic per block
    int inc = cntP;
#pragma unroll
    for (int d = 1; d < 32; d <<= 1) {
        int t = __shfl_up_sync(0xffffffffu, inc, d);
        if (lane >= d) inc += t;
    }
    if (lane == 31) wtot[wd] = inc;
    __syncthreads();
    if (tid == 0) {
        int tot = 0;
#pragma unroll
        for (int w = 0; w < 8; w++) { int t = wtot[w]; wtot[w] = tot; tot += t; }
        sBase = tot ? atomicAdd(&g_pcnt[b], tot) : 0;
    }
    __syncthreads();
    if (act && cntP) {
        int off = sBase + wtot[wd] + (inc - cntP);
#pragma unroll
        for (int q = 0; q < 8; q++) {
            if (kb[q] >= PRE_BITS) {
                if (off < PRE_CAP)
                    g_pre[b * PRE_CAP + off] = ((unsigned long long)kb[q] << 32) | (unsigned)(base + q);
                else
                    g_pover[b] = 1;
                off++;
            }
        }
    }
}

// ---------------- threshold finder over a shared histogram ----------------
__device__ __forceinline__ void find_thresh(const int* h, int nbins, int target,
                                            int* partial, int* res, int tid,
                                            int& T, int& acc) {
    int spb = nbins >> 8;
    if (tid < 256) { int s = 0; for (int i = 0; i < spb; i++) s += h[tid * spb + i]; partial[tid] = s; }
    __syncthreads();
    if (tid == 0) {
        int a = 0, TT = 0;
        for (int seg = 255; seg >= 0; seg--) {
            int ps = partial[seg];
            if (a + ps >= target) {
                for (int bin = seg * spb + spb - 1;; bin--) {
                    int hc = h[bin];
                    if (a + hc >= target) { TT = bin; break; }
                    a += hc;
                }
                break;
            }
            a += ps;
        }
        res[0] = TT; res[1] = a;
    }
    __syncthreads();
    T = res[0]; acc = res[1];
}

// ---------------- ballot-aggregated emit into shared cand ----------------
__device__ __forceinline__ void emit_sh(bool em, unsigned k, unsigned a,
                                        unsigned long long* cand, int* sCnt, int lane) {
    unsigned mv = __ballot_sync(0xffffffffu, em);
    if (mv) {
        int ldr = __ffs(mv) - 1;
        int pos = 0;
        if (lane == ldr) pos = atomicAdd(sCnt, __popc(mv));
        pos = __shfl_sync(0xffffffffu, pos, ldr);
        if (em) {
            int o = pos + __popc(mv & ((1u << lane) - 1));
            if (o < 1024)
                cand[o] = ((unsigned long long)(~k) << 32) | a;  // asc sort = desc score, asc idx
        }
    }
}

// ---------------- kernel 2: fused select + sort + winner decode (per batch) ----------------
__global__ void __launch_bounds__(1024) topk_kernel(Ptrs in) {
    __shared__ int h[4096];
    __shared__ int partial[256];
    __shared__ int res[2];
    __shared__ int h3[256];
    __shared__ int sCnt, sHi;
    __shared__ unsigned long long cand[1024];
    int b = blockIdx.x, tid = threadIdx.x, lane = tid & 31;

    int pcnt = min(g_pcnt[b], PRE_CAP);
    bool usable = (pcnt >= 1000) && (g_pover[b] == 0);
    const unsigned long long* pre = g_pre + b * PRE_CAP;
    const float* sc = g_score + b * NA;

    for (int i = tid; i < 4096; i += 1024) h[i] = 0;
    if (tid < 256) h3[tid] = 0;
    if (tid == 0) { sCnt = 0; sHi = 0; }
    __syncthreads();

    // ---- stage 0: determine T1 / acc1 ----
    int T1, acc1;
    if (usable) {
        // every prelist item has bin >= 0x3F7; count bins > 0x3F7 (score==1.0f, ~never)
        int c = 0;
        for (int i = tid; i < pcnt; i += 1024)
            c += ((unsigned)(pre[i] >> 32) >= 0x3F800000u);
#pragma unroll
        for (int d = 16; d > 0; d >>= 1) c += __shfl_down_sync(0xffffffffu, c, d);
        if (lane == 0 && c) atomicAdd(&sHi, c);
    }
    __syncthreads();
    if (usable && sHi < 1000) {
        T1 = 0x3F7; acc1 = sHi;
    } else {
        usable = false;
        // fallback: full-scan 12-bit histogram, warp-aggregated (hot bins!)
        for (int it = 0; it < 48; it++) {
            int i = it * 1024 + tid;
            bool v = i < NA;
            unsigned bal = __ballot_sync(0xffffffffu, v);
            if (v) {
                int bin = (int)(__float_as_uint(sc[i]) >> 20);
                unsigned mm = __match_any_sync(bal, bin);
                if (lane == (int)(__ffs(mm) - 1)) atomicAdd(&h[bin], __popc(mm));
            }
        }
        __syncthreads();
        find_thresh(h, 4096, 1000, partial, res, tid, T1, acc1);
        __syncthreads();
        for (int i = tid; i < 4096; i += 1024) h[i] = 0;
        __syncthreads();
    }

    int nIt = usable ? ((pcnt + 1023) >> 10) : 48;

    // ---- stage 1: emit bin>T1 ; hist mid-12 for bin==T1 ----
    for (int it = 0; it < nIt; it++) {
        int i = it * 1024 + tid;
        unsigned k = 0, a = 0; bool em = false;
        if (usable) {
            if (i < pcnt) { unsigned long long v = pre[i]; k = (unsigned)(v >> 32); a = (unsigned)v; }
        } else if (i < NA) { k = __float_as_uint(sc[i]); a = (unsigned)i; }
        if (k) {
            int bin = (int)(k >> 20);
            if (bin > T1) em = true;
            else if (bin == T1) atomicAdd(&h[(k >> 8) & 0xFFF], 1);
        }
        emit_sh(em, k, a, cand, &sCnt, lane);
    }
    __syncthreads();
    int T2, acc2;
    find_thresh(h, 4096, 1000 - acc1, partial, res, tid, T2, acc2);
    __syncthreads();

    // ---- stage 2: low-byte hist for bin==T1 && mid==T2 ----
    for (int it = 0; it < nIt; it++) {
        int i = it * 1024 + tid;
        unsigned k = 0;
        if (usable) { if (i < pcnt) k = (unsigned)(pre[i] >> 32); }
        else if (i < NA) k = __float_as_uint(sc[i]);
        if (k && (int)(k >> 20) == T1 && (int)((k >> 8) & 0xFFF) == T2)
            atomicAdd(&h3[k & 0xFF], 1);
    }
    __syncthreads();
    if (tid == 0) {
        int tg = 1000 - acc1 - acc2, a = 0, T = 0;
        for (int bin = 255;; bin--) {
            int hc = h3[bin];
            if (a + hc >= tg) { T = bin; break; }
            a += hc;
        }
        res[0] = T;
    }
    __syncthreads();
    int T3 = res[0];

    // ---- stage 3: emit remainder ----
    for (int it = 0; it < nIt; it++) {
        int i = it * 1024 + tid;
        unsigned k = 0, a = 0; bool em = false;
        if (usable) {
            if (i < pcnt) { unsigned long long v = pre[i]; k = (unsigned)(v >> 32); a = (unsigned)v; }
        } else if (i < NA) { k = __float_as_uint(sc[i]); a = (unsigned)i; }
        if (k && (int)(k >> 20) == T1) {
            int mid = (int)((k >> 8) & 0xFFF);
            em = (mid > T2) || (mid == T2 && (int)(k & 0xFF) >= T3);
        }
        emit_sh(em, k, a, cand, &sCnt, lane);
    }
    __syncthreads();
    int c = min(sCnt, 1024);
    if (tid >= c) cand[tid] = 0xFFFFFFFFFFFFFFFFULL;
    __syncthreads();

    // ---- stage 4: bitonic sort 1024 ascending ----
    for (int k2 = 2; k2 <= 32; k2 <<= 1) {
        for (int s2 = k2 >> 1; s2 > 0; s2 >>= 1) {
            __syncwarp();
            int q = tid ^ s2;
            if (q > tid) {
                bool asc = ((tid & k2) == 0);
                unsigned long long A = cand[tid], Bv = cand[q];
                if ((A > Bv) == asc) { cand[tid] = Bv; cand[q] = A; }
            }
        }
    }
    for (int k2 = 64; k2 <= 1024; k2 <<= 1) {
        for (int s2 = k2 >> 1; s2 > 0; s2 >>= 1) {
            if (s2 >= 16) __syncthreads(); else __syncwarp();
            int q = tid ^ s2;
            if (q > tid) {
                bool asc = ((tid & k2) == 0);
                unsigned long long A = cand[tid], Bv = cand[q];
                if ((A > Bv) == asc) { cand[tid] = Bv; cand[q] = A; }
            }
        }
    }
    __syncthreads();

    // ---- stage 5: winner decode ----
    int o = b * 1024 + tid;
    if (tid < 1000 && tid < c) {
        unsigned long long v = cand[tid];
        int a = (int)(unsigned)(v & 0xFFFFFFFFu);
        float score = __uint_as_float(~(unsigned)(v >> 32));

        int l, p, h2, s; level_of(a, l, p, h2, s);
        int hh = h2 * h2;
        const float* cls = in.p[l]      + b * 15 * hh + p;
        const float* reg = in.p[5 + l]  + b * 5  * hh + p;
        const float* tcp = in.p[10 + l] + b * 18 * hh + p;
        const float* trp = in.p[15 + l] + b * hh + p;

        float best = cls[0]; int bc = 0;
#pragma unroll
        for (int cc = 1; cc < 15; cc++) { float vv = cls[cc * hh]; if (vv > best) { best = vv; bc = cc; } }
        float tb = tcp[0]; int ta = 0;
#pragma unroll
        for (int cc = 1; cc < 18; cc++) { float vv = tcp[cc * hh]; if (vv > tb) { tb = vv; ta = cc; } }
        float theta = (float)(ta + 1) * 10.0f + trp[0];

        float fs = (float)s;
        int col = p % h2, row = p / h2;
        float x = (float)col * fs + (float)(s / 2);
        float y = (float)row * fs + (float)(s / 2);

        g_topScore[o] = score;
        g_topCls[o]   = (float)(bc + 1);
        g_topTheta[o] = theta;
        g_topBox[o * 4 + 0] = x - reg[0] * fs;
        g_topBox[o * 4 + 1] = y - reg[hh] * fs;
        g_topBox[o * 4 + 2] = x + reg[2 * hh] * fs;
        g_topBox[o * 4 + 3] = y + reg[3 * hh] * fs;
    } else {
        g_topScore[o] = -1e30f;
        g_topCls[o] = 0.f; g_topTheta[o] = 0.f;
        g_topBox[o * 4 + 0] = 0.f; g_topBox[o * 4 + 1] = 0.f;
        g_topBox[o * 4 + 2] = 0.f; g_topBox[o * 4 + 3] = 0.f;
    }
}

// ---------------- kernel 3: IoU bit-masks (fully parallel) ----------------
__global__ void __launch_bounds__(1024) mask_kernel() {
    int b = blockIdx.y, g = blockIdx.x, j = threadIdx.x;
    __shared__ float ib[32][4];
    if (j < 32) {
#pragma unroll
        for (int k = 0; k < 4; k++) ib[j][k] = g_topBox[(b * 1024 + g * 32 + j) * 4 + k];
    }
    __syncthreads();

    float x1 = g_topBox[(b * 1024 + j) * 4 + 0];
    float y1 = g_topBox[(b * 1024 + j) * 4 + 1];
    float x2 = g_topBox[(b * 1024 + j) * 4 + 2];
    float y2 = g_topBox[(b * 1024 + j) * 4 + 3];
    float area = fmaxf(x2 - x1, 0.f) * fmaxf(y2 - y1, 0.f);

    unsigned w = 0;
#pragma unroll
    for (int bb = 0; bb < 32; bb++) {
        int i = g * 32 + bb;
        float ix1 = ib[bb][0], iy1 = ib[bb][1], ix2 = ib[bb][2], iy2 = ib[bb][3];
        float iarea = fmaxf(ix2 - ix1, 0.f) * fmaxf(iy2 - iy1, 0.f);
        float iw = fmaxf(fminf(x2, ix2) - fmaxf(x1, ix1), 0.f);
        float ih = fmaxf(fminf(y2, iy2) - fmaxf(y1, iy1), 0.f);
        float inter = iw * ih;
        float uni = fmaxf(area + iarea - inter, 1e-8f);
        bool pred = (inter > 0.3f * uni) && (i < j);
        w |= ((unsigned)pred) << bb;
    }
    g_W[(b * 32 + g) * 1024 + j] = w;

    if ((j >> 5) == g) {
        int lane = j & 31;
        unsigned u = 0;
#pragma unroll
        for (int i = 0; i < 32; i++) {
            unsigned t = __ballot_sync(0xffffffffu, (w >> i) & 1u);
            if (lane == i) u = t;
        }
        g_U[b * 1024 + g * 32 + lane] = u;
    }
}

// ---------------- kernel 4: barrier-free pipelined greedy scan + output ----------------
__global__ void __launch_bounds__(1024) scan_kernel(float* __restrict__ out) {
    int b = blockIdx.x, j = threadIdx.x;
    int lane = j & 31, wid = j >> 5;
    __shared__ unsigned su[1024];
    __shared__ unsigned long long sm64[32];

    float score = g_topScore[b * 1024 + j];
    bool alive = (j < 1000) && (score >= 0.05f);

    unsigned su_own = g_U[b * 1024 + j];
    su[j] = su_own;
    if (j < 32) sm64[j] = 0ULL;
    unsigned nzm = __ballot_sync(0xffffffffu, su_own != 0u);
    __syncthreads();

    const unsigned* Wb = g_W + b * 32 * 1024;
    for (int g = 0; g < wid; g++) {
        unsigned wv = Wb[g * 1024 + j];
        unsigned long long v;
        do { v = *(volatile const unsigned long long*)&sm64[g]; } while (!(v >> 32));
        unsigned mg = (unsigned)v;
        alive = alive && ((wv & mg) == 0u);
    }
    unsigned m = __ballot_sync(0xffffffffu, alive);
    if (lane == 0) {
        unsigned todo = nzm & m;
        while (todo) {
            int bb = __ffs(todo) - 1;
            m &= ~su[wid * 32 + bb];
            todo &= todo - 1;
            todo &= m;
        }
        *(volatile unsigned long long*)&sm64[wid] = (1ULL << 32) | (unsigned long long)m;
    }
    m = __shfl_sync(0xffffffffu, m, 0);
    alive = (m >> lane) & 1u;

    if (j < 1000) {
        float k = alive ? 1.0f : 0.0f;
        int o = b * 1024 + j;
        out[b * 1000 + j] = score * k;
        out[16000 + b * 1000 + j] = k * g_topCls[o];
        int base = 32000 + (b * 1000 + j) * 5;
        out[base + 0] = k * g_topBox[o * 4 + 0];
        out[base + 1] = k * g_topBox[o * 4 + 1];
        out[base + 2] = k * g_topBox[o * 4 + 2];
        out[base + 3] = k * g_topBox[o * 4 + 3];
        out[base + 4] = k * g_topTheta[o];
    }
}

// ---------------- launch ----------------
extern "C" void kernel_launch(void* const* d_in, const int* in_sizes, int n_in,
                              void* d_out, int out_size) {
    Ptrs P;
    for (int i = 0; i < 20; i++) P.p[i] = (const float*)d_in[i];

    zero_kernel<<<1, 32>>>();
    score_pre_kernel<<<dim3(24, NB), 256>>>(P);
    topk_kernel<<<NB, 1024>>>(P);
    mask_kernel<<<dim3(32, NB), 1024>>>();
    scan_kernel<<<NB, 1024>>>((float*)d_out);
}